// round 15
// baseline (speedup 1.0000x reference)
#include <cuda_runtime.h>
#include <math.h>

#define NB 16
#define HW 3136
#define CC 256
#define OH 224
#define OW 224
#define RR 16
#define KS 33
#define NOUT (NB*OH*OW)

__device__ float g_mask56[NB * HW];
__device__ float g_tmp[NOUT];

// ---------------------------------------------------------------------------
// One fully-unrolled segment of the padded triangular schedule.
// Per slot: mask B (triangular weight, hoisted dw), cvt, ring prefetch of
// slot kt+4 into registers, L2 PREFETCH of slot kt+8 (prefetch.global.L2:
// no register, no scoreboard -> converts the ring load's miss path from
// DRAM ~600cyc to L2 ~250cyc, which the 4-slot ring DOES cover), LDS.128
// A fragment, 1 MMA. All addressing compile-time after unroll.
// For every segment, slot kt+4 and kt+8 land in seg_base or next_base with
// compile-time offsets (tail overshoot re-touches already-fetched lines).
// ---------------------------------------------------------------------------
template <int NT, int SEGLEN>
__device__ __forceinline__ void run_segment(
    const float* seg_base, const float* next_base, const uint4* sdA,
    int j, float dw0, float dw1, int lane,
    float* r0, float* r1, float* c0, float* c1, float* c2, float* c3) {
#pragma unroll
  for (int kt = 0; kt < SEGLEN; kt++) {
    const int u = kt & 3;
    float b0 = r0[u], b1 = r1[u];
    // ring prefetch: slot kt+4
    const float* np = (kt + 4 < SEGLEN)
                          ? (seg_base + (kt + 4) * (8 * CC))
                          : (next_base + (kt + 4 - SEGLEN) * (8 * CC));
    r0[u] = np[0];
    r1[u] = np[4 * CC];
    // L2 prefetch: slot kt+8 (both rows; register-free, scoreboard-free)
    const float* pp = (kt + 8 < SEGLEN)
                          ? (seg_base + (kt + 8) * (8 * CC))
                          : (next_base + (kt + 8 - SEGLEN) * (8 * CC));
    asm volatile("prefetch.global.L2 [%0];" :: "l"(pp));
    asm volatile("prefetch.global.L2 [%0];" :: "l"(pp + 4 * CC));
    // triangular weight (j runtime; kt compile-time)
    const float s0 = (kt < j) ? 1.f : ((kt == j) ? dw0 : 0.f);
    const float s1 = (kt < j) ? 1.f : ((kt == j) ? dw1 : 0.f);
    b0 *= s0;
    b1 *= s1;
    unsigned bh0, bh1;
    asm("cvt.rna.tf32.f32 %0, %1;" : "=r"(bh0) : "f"(b0));
    asm("cvt.rna.tf32.f32 %0, %1;" : "=r"(bh1) : "f"(b1));
    const uint4 a = sdA[kt * 32 + lane];
    asm("mma.sync.aligned.m16n8k8.row.col.f32.tf32.tf32.f32 "
        "{%0,%1,%2,%3}, {%4,%5,%6,%7}, {%8,%9}, {%0,%1,%2,%3};"
        : "+f"(c0[NT]), "+f"(c1[NT]), "+f"(c2[NT]), "+f"(c3[NT])
        : "r"(a.x), "r"(a.y), "r"(a.z), "r"(a.w), "r"(bh0), "r"(bh1));
  }
}

// ---------------------------------------------------------------------------
// Kernel 1: per-pixel Mahalanobis via tensor cores + symmetry, slot-uniform
// padded triangular schedule, fully unrolled, with 2-level prefetch
// (registers at +4 slots, L2 at +8 slots). quad = 2 * sum (diag weight 1/2).
// ---------------------------------------------------------------------------
__global__ __launch_bounds__(256, 4) void maha_kernel(
    const float* __restrict__ x, const float* __restrict__ mean,
    const float* __restrict__ M) {
  const int p = blockIdx.x;
  const int t = threadIdx.x;
  const int wid = t >> 5, lane = t & 31;
  const int tq = lane & 3;    // k-offset within fragment
  const int tr = lane >> 2;   // row/col group index
  __shared__ float sd[CC][NB];      // diff: sd[channel][batch]   (16 KB)
  __shared__ uint4 sdA[32 * 32];    // A fragments, tf32, frag order (16 KB)
  __shared__ float red[8][NB];

  {
    const float mu = mean[p * CC + t];
    const float* xp = x + (size_t)p * CC + t;
#pragma unroll
    for (int b = 0; b < NB; b++)
      sd[t][b] = xp[(size_t)b * ((size_t)HW * CC)] - mu;
  }
  __syncthreads();

  // stage all 32 A fragments (pre-converted to tf32)
#pragma unroll
  for (int s2 = 0; s2 < 4; s2++) {
    const int kt = wid + s2 * 8;
    unsigned x0, x1, x2, x3;
    asm("cvt.rna.tf32.f32 %0, %1;" : "=r"(x0) : "f"(sd[kt * 8 + tq][tr]));
    asm("cvt.rna.tf32.f32 %0, %1;" : "=r"(x1) : "f"(sd[kt * 8 + tq][tr + 8]));
    asm("cvt.rna.tf32.f32 %0, %1;" : "=r"(x2) : "f"(sd[kt * 8 + tq + 4][tr]));
    asm("cvt.rna.tf32.f32 %0, %1;" : "=r"(x3) : "f"(sd[kt * 8 + tq + 4][tr + 8]));
    sdA[kt * 32 + lane] = make_uint4(x0, x1, x2, x3);
  }
  __syncthreads();

  const float* Mp = M + ((size_t)p << 16);
  const int w = wid;

  // diagonal-tile lane weights (kt-invariant, hoisted)
  const float dw0 = (tq < tr) ? 1.f : (tq == tr) ? 0.5f : 0.f;
  const float dw1 = (tq + 4 < tr) ? 1.f : (tq + 4 == tr) ? 0.5f : 0.f;

  // segment base pointers: base(j) = Mp + tq*CC + j*8 + tr
  const float* tb = Mp + tq * CC + tr;
  const float* sb0 = tb + w * 8;
  const float* sb1 = tb + (15 - w) * 8;
  const float* sb2 = tb + (16 + w) * 8;
  const float* sb3 = tb + (31 - w) * 8;

  float c0[4], c1[4], c2[4], c3[4];
#pragma unroll
  for (int nt = 0; nt < 4; nt++) { c0[nt] = c1[nt] = c2[nt] = c3[nt] = 0.f; }

  // prologue: ring slots 0..3 (segment 0; kt>j harmless, masked later)
  float r0[4], r1[4];
#pragma unroll
  for (int u = 0; u < 4; u++) {
    const float* ptr = sb0 + u * (8 * CC);
    r0[u] = ptr[0];
    r1[u] = ptr[4 * CC];
  }

  run_segment<0, 8>(sb0, sb1, sdA, w, dw0, dw1, lane, r0, r1, c0, c1, c2, c3);
  run_segment<1, 16>(sb1, sb2, sdA, 15 - w, dw0, dw1, lane, r0, r1, c0, c1, c2, c3);
  run_segment<2, 24>(sb2, sb3, sdA, 16 + w, dw0, dw1, lane, r0, r1, c0, c1, c2, c3);
  run_segment<3, 32>(sb3, sb3, sdA, 31 - w, dw0, dw1, lane, r0, r1, c0, c1, c2, c3);

  // ---- epilogue: q[b] += V[b,n] * d[b,n]; quad = 2 * total ----
  // C frag: c0:(tr, 2tq) c1:(tr, 2tq+1) c2:(tr+8, 2tq) c3:(tr+8, 2tq+1)
  const int jl[4] = {w, 15 - w, 16 + w, 31 - w};
  float q0 = 0.f, q1 = 0.f;
#pragma unroll
  for (int nt = 0; nt < 4; nt++) {
    const int n = jl[nt] * 8 + tq * 2;
    q0 += c0[nt] * sd[n][tr]     + c1[nt] * sd[n + 1][tr];
    q1 += c2[nt] * sd[n][tr + 8] + c3[nt] * sd[n + 1][tr + 8];
  }
  q0 += __shfl_xor_sync(0xffffffffu, q0, 1);
  q0 += __shfl_xor_sync(0xffffffffu, q0, 2);
  q1 += __shfl_xor_sync(0xffffffffu, q1, 1);
  q1 += __shfl_xor_sync(0xffffffffu, q1, 2);
  if (tq == 0) {
    red[wid][tr] = q0;
    red[wid][tr + 8] = q1;
  }
  __syncthreads();
  if (t < NB) {
    float s = 0.f;
#pragma unroll
    for (int ww = 0; ww < 8; ww++) s += red[ww][t];
    g_mask56[t * HW + p] = sqrtf(fmaxf(2.0f * s, 0.f));
  }
}

__device__ __forceinline__ int reflect101(int i) {
  if (i < 0) i = -i;
  if (i > 223) i = 446 - i;
  return i;
}

__device__ __forceinline__ void load_weights(float* w, float* inv) {
  const int tid = threadIdx.x;
  if (tid < KS) {
    const float d = (float)(tid - RR);
    w[tid] = expf(-(d * d) / 32.0f);
  }
  __syncthreads();
  if (tid == 0) {
    float s = 0.f;
    for (int j = 0; j < KS; j++) s += w[j];
    *inv = 1.0f / s;
  }
}

// ---------------------------------------------------------------------------
// Kernel 2: FUSED bilinear resize (56->224) + vertical blur; zeroes scores.
// ---------------------------------------------------------------------------
__global__ __launch_bounds__(256) void blur_v_kernel(float* __restrict__ score) {
  __shared__ float s[OH + 32][17];
  __shared__ float w[KS];
  __shared__ float inv;
  load_weights(w, &inv);
  const int tid = threadIdx.x;
  if (blockIdx.x == 0 && tid < NB) score[tid] = 0.0f;
  const int b = blockIdx.x / 14;
  const int xt = (blockIdx.x % 14) * 16;
  const float* mp = g_mask56 + b * HW;
#pragma unroll
  for (int li = tid; li < (OH + 32) * 16; li += 256) {
    const int r = li >> 4, c = li & 15;
    const int gy = reflect101(r - RR);
    const int gx = xt + c;
    const float fy = (gy + 0.5f) * 0.25f - 0.5f;
    const float fx = (gx + 0.5f) * 0.25f - 0.5f;
    const int y0 = (int)floorf(fy);
    const int x0 = (int)floorf(fx);
    const float wy = fy - (float)y0;
    const float wx = fx - (float)x0;
    const int y0c = min(max(y0, 0), 55), y1c = min(max(y0 + 1, 0), 55);
    const int x0c = min(max(x0, 0), 55), x1c = min(max(x0 + 1, 0), 55);
    const float v00 = mp[y0c * 56 + x0c];
    const float v01 = mp[y0c * 56 + x1c];
    const float v10 = mp[y1c * 56 + x0c];
    const float v11 = mp[y1c * 56 + x1c];
    s[r][c] = (1.f - wy) * ((1.f - wx) * v00 + wx * v01) +
              wy * ((1.f - wx) * v10 + wx * v11);
  }
  __syncthreads();
  float* dst = g_tmp + b * OH * OW + xt;
  const int c = tid & 15;
  for (int y = tid >> 4; y < OH; y += 16) {
    float sum = 0.f;
#pragma unroll
    for (int j = 0; j < KS; j++) sum += w[j] * s[y + j][c];
    dst[y * OW + c] = sum * inv;
  }
}

// ---------------------------------------------------------------------------
// Kernel 3: horizontal blur + per-batch max.
// ---------------------------------------------------------------------------
__global__ __launch_bounds__(256) void blur_h_kernel(float* __restrict__ out_mask,
                                                     float* __restrict__ score) {
  __shared__ float s[8][256];
  __shared__ float w[KS];
  __shared__ float inv;
  __shared__ float smx[8];
  load_weights(w, &inv);
  const int tid = threadIdx.x;
  const int b = blockIdx.x / 28;
  const int yt = (blockIdx.x % 28) * 8;
  const float* src = g_tmp + (b * OH + yt) * OW;
#pragma unroll
  for (int li = tid; li < 8 * 256; li += 256) {
    const int r = li >> 8, c = li & 255;
    const int gx = reflect101(c - RR);
    s[r][c] = src[r * OW + gx];
  }
  __syncthreads();
  float* dst = out_mask + (b * OH + yt) * OW;
  const int lane = tid & 31;
  const int r = tid >> 5;
  float mx = 0.f;
#pragma unroll
  for (int x0 = 0; x0 < OW; x0 += 32) {
    const int x = x0 + lane;
    float sum = 0.f;
#pragma unroll
    for (int j = 0; j < KS; j++) sum += w[j] * s[r][x + j];
    sum *= inv;
    dst[r * OW + x] = sum;
    mx = fmaxf(mx, sum);
  }
#pragma unroll
  for (int off = 16; off > 0; off >>= 1)
    mx = fmaxf(mx, __shfl_down_sync(0xffffffffu, mx, off));
  if (lane == 0) smx[r] = mx;
  __syncthreads();
  if (tid == 0) {
    float m2 = smx[0];
#pragma unroll
    for (int k = 1; k < 8; k++) m2 = fmaxf(m2, smx[k]);
    atomicMax((int*)&score[b], __float_as_int(m2));
  }
}

extern "C" void kernel_launch(void* const* d_in, const int* in_sizes, int n_in,
                              void* d_out, int out_size) {
  const float* inputs = (const float*)d_in[0];    // [16,56,56,256]
  const float* mean = (const float*)d_in[1];      // [3136,256]
  const float* cvar_inv = (const float*)d_in[2];  // [3136,256,256]
  float* out = (float*)d_out;
  float* score = out;          // [16,1]
  float* mask = out + NB;      // [16,224,224,1]

  maha_kernel<<<HW, 256>>>(inputs, mean, cvar_inv);
  blur_v_kernel<<<16 * 14, 256>>>(score);
  blur_h_kernel<<<16 * 28, 256>>>(mask, score);
}

// round 16
// speedup vs baseline: 1.6156x; 1.6156x over previous
#include <cuda_runtime.h>
#include <math.h>

#define NB 16
#define HW 3136
#define CC 256
#define OH 224
#define OW 224
#define RR 16
#define KS 33
#define NOUT (NB*OH*OW)

__device__ float g_mask56[NB * HW];
__device__ float g_tmp[NOUT];

// ---------------------------------------------------------------------------
// One fully-unrolled segment of the padded triangular schedule (R14 winner).
// Per slot: mask B (triangular weight, hoisted dw), cvt, ring prefetch of
// slot kt+4 into registers via __ldcs (evict-first: M has zero reuse, keep
// the stream from displacing useful L2/L1 state), LDS.128 A fragment, 1 MMA.
// All addressing compile-time after unroll.
// ---------------------------------------------------------------------------
template <int NT, int SEGLEN>
__device__ __forceinline__ void run_segment(
    const float* seg_base, const float* next_base, const uint4* sdA,
    int j, float dw0, float dw1, int lane,
    float* r0, float* r1, float* c0, float* c1, float* c2, float* c3) {
#pragma unroll
  for (int kt = 0; kt < SEGLEN; kt++) {
    const int u = kt & 3;
    float b0 = r0[u], b1 = r1[u];
    // ring prefetch: slot kt+4 (compile-time base select + immediate offset)
    const float* np = (kt + 4 < SEGLEN)
                          ? (seg_base + (kt + 4) * (8 * CC))
                          : (next_base + (kt + 4 - SEGLEN) * (8 * CC));
    r0[u] = __ldcs(np);
    r1[u] = __ldcs(np + 4 * CC);
    // triangular weight (j runtime; kt compile-time)
    const float s0 = (kt < j) ? 1.f : ((kt == j) ? dw0 : 0.f);
    const float s1 = (kt < j) ? 1.f : ((kt == j) ? dw1 : 0.f);
    b0 *= s0;
    b1 *= s1;
    unsigned bh0, bh1;
    asm("cvt.rna.tf32.f32 %0, %1;" : "=r"(bh0) : "f"(b0));
    asm("cvt.rna.tf32.f32 %0, %1;" : "=r"(bh1) : "f"(b1));
    const uint4 a = sdA[kt * 32 + lane];
    asm("mma.sync.aligned.m16n8k8.row.col.f32.tf32.tf32.f32 "
        "{%0,%1,%2,%3}, {%4,%5,%6,%7}, {%8,%9}, {%0,%1,%2,%3};"
        : "+f"(c0[NT]), "+f"(c1[NT]), "+f"(c2[NT]), "+f"(c3[NT])
        : "r"(a.x), "r"(a.y), "r"(a.z), "r"(a.w), "r"(bh0), "r"(bh1));
  }
}

// ---------------------------------------------------------------------------
// Kernel 1: per-pixel Mahalanobis via tensor cores + symmetry, slot-uniform
// padded triangular schedule, fully unrolled, 4-deep register ring.
// quad = 2 * sum (diagonal at weight 1/2).
// ---------------------------------------------------------------------------
__global__ __launch_bounds__(256, 4) void maha_kernel(
    const float* __restrict__ x, const float* __restrict__ mean,
    const float* __restrict__ M) {
  const int p = blockIdx.x;
  const int t = threadIdx.x;
  const int wid = t >> 5, lane = t & 31;
  const int tq = lane & 3;    // k-offset within fragment
  const int tr = lane >> 2;   // row/col group index
  __shared__ float sd[CC][NB];      // diff: sd[channel][batch]   (16 KB)
  __shared__ uint4 sdA[32 * 32];    // A fragments, tf32, frag order (16 KB)
  __shared__ float red[8][NB];

  {
    const float mu = mean[p * CC + t];
    const float* xp = x + (size_t)p * CC + t;
#pragma unroll
    for (int b = 0; b < NB; b++)
      sd[t][b] = xp[(size_t)b * ((size_t)HW * CC)] - mu;
  }
  __syncthreads();

  // stage all 32 A fragments (pre-converted to tf32)
#pragma unroll
  for (int s2 = 0; s2 < 4; s2++) {
    const int kt = wid + s2 * 8;
    unsigned x0, x1, x2, x3;
    asm("cvt.rna.tf32.f32 %0, %1;" : "=r"(x0) : "f"(sd[kt * 8 + tq][tr]));
    asm("cvt.rna.tf32.f32 %0, %1;" : "=r"(x1) : "f"(sd[kt * 8 + tq][tr + 8]));
    asm("cvt.rna.tf32.f32 %0, %1;" : "=r"(x2) : "f"(sd[kt * 8 + tq + 4][tr]));
    asm("cvt.rna.tf32.f32 %0, %1;" : "=r"(x3) : "f"(sd[kt * 8 + tq + 4][tr + 8]));
    sdA[kt * 32 + lane] = make_uint4(x0, x1, x2, x3);
  }
  __syncthreads();

  const float* Mp = M + ((size_t)p << 16);
  const int w = wid;

  // diagonal-tile lane weights (kt-invariant, hoisted)
  const float dw0 = (tq < tr) ? 1.f : (tq == tr) ? 0.5f : 0.f;
  const float dw1 = (tq + 4 < tr) ? 1.f : (tq + 4 == tr) ? 0.5f : 0.f;

  // segment base pointers: base(j) = Mp + tq*CC + j*8 + tr
  const float* tb = Mp + tq * CC + tr;
  const float* sb0 = tb + w * 8;
  const float* sb1 = tb + (15 - w) * 8;
  const float* sb2 = tb + (16 + w) * 8;
  const float* sb3 = tb + (31 - w) * 8;

  float c0[4], c1[4], c2[4], c3[4];
#pragma unroll
  for (int nt = 0; nt < 4; nt++) { c0[nt] = c1[nt] = c2[nt] = c3[nt] = 0.f; }

  // prologue: ring slots 0..3 (segment 0; kt>j harmless, masked later)
  float r0[4], r1[4];
#pragma unroll
  for (int u = 0; u < 4; u++) {
    const float* ptr = sb0 + u * (8 * CC);
    r0[u] = __ldcs(ptr);
    r1[u] = __ldcs(ptr + 4 * CC);
  }

  run_segment<0, 8>(sb0, sb1, sdA, w, dw0, dw1, lane, r0, r1, c0, c1, c2, c3);
  run_segment<1, 16>(sb1, sb2, sdA, 15 - w, dw0, dw1, lane, r0, r1, c0, c1, c2, c3);
  run_segment<2, 24>(sb2, sb3, sdA, 16 + w, dw0, dw1, lane, r0, r1, c0, c1, c2, c3);
  run_segment<3, 32>(sb3, sb3, sdA, 31 - w, dw0, dw1, lane, r0, r1, c0, c1, c2, c3);

  // ---- epilogue: q[b] += V[b,n] * d[b,n]; quad = 2 * total ----
  // C frag: c0:(tr, 2tq) c1:(tr, 2tq+1) c2:(tr+8, 2tq) c3:(tr+8, 2tq+1)
  const int jl[4] = {w, 15 - w, 16 + w, 31 - w};
  float q0 = 0.f, q1 = 0.f;
#pragma unroll
  for (int nt = 0; nt < 4; nt++) {
    const int n = jl[nt] * 8 + tq * 2;
    q0 += c0[nt] * sd[n][tr]     + c1[nt] * sd[n + 1][tr];
    q1 += c2[nt] * sd[n][tr + 8] + c3[nt] * sd[n + 1][tr + 8];
  }
  q0 += __shfl_xor_sync(0xffffffffu, q0, 1);
  q0 += __shfl_xor_sync(0xffffffffu, q0, 2);
  q1 += __shfl_xor_sync(0xffffffffu, q1, 1);
  q1 += __shfl_xor_sync(0xffffffffu, q1, 2);
  if (tq == 0) {
    red[wid][tr] = q0;
    red[wid][tr + 8] = q1;
  }
  __syncthreads();
  if (t < NB) {
    float s = 0.f;
#pragma unroll
    for (int ww = 0; ww < 8; ww++) s += red[ww][t];
    g_mask56[t * HW + p] = sqrtf(fmaxf(2.0f * s, 0.f));
  }
}

__device__ __forceinline__ int reflect101(int i) {
  if (i < 0) i = -i;
  if (i > 223) i = 446 - i;
  return i;
}

__device__ __forceinline__ void load_weights(float* w, float* inv) {
  const int tid = threadIdx.x;
  if (tid < KS) {
    const float d = (float)(tid - RR);
    w[tid] = expf(-(d * d) / 32.0f);
  }
  __syncthreads();
  if (tid == 0) {
    float s = 0.f;
    for (int j = 0; j < KS; j++) s += w[j];
    *inv = 1.0f / s;
  }
}

// ---------------------------------------------------------------------------
// Kernel 2: FUSED bilinear resize (56->224) + vertical blur; zeroes scores.
// ---------------------------------------------------------------------------
__global__ __launch_bounds__(256) void blur_v_kernel(float* __restrict__ score) {
  __shared__ float s[OH + 32][17];
  __shared__ float w[KS];
  __shared__ float inv;
  load_weights(w, &inv);
  const int tid = threadIdx.x;
  if (blockIdx.x == 0 && tid < NB) score[tid] = 0.0f;
  const int b = blockIdx.x / 14;
  const int xt = (blockIdx.x % 14) * 16;
  const float* mp = g_mask56 + b * HW;
#pragma unroll
  for (int li = tid; li < (OH + 32) * 16; li += 256) {
    const int r = li >> 4, c = li & 15;
    const int gy = reflect101(r - RR);
    const int gx = xt + c;
    const float fy = (gy + 0.5f) * 0.25f - 0.5f;
    const float fx = (gx + 0.5f) * 0.25f - 0.5f;
    const int y0 = (int)floorf(fy);
    const int x0 = (int)floorf(fx);
    const float wy = fy - (float)y0;
    const float wx = fx - (float)x0;
    const int y0c = min(max(y0, 0), 55), y1c = min(max(y0 + 1, 0), 55);
    const int x0c = min(max(x0, 0), 55), x1c = min(max(x0 + 1, 0), 55);
    const float v00 = mp[y0c * 56 + x0c];
    const float v01 = mp[y0c * 56 + x1c];
    const float v10 = mp[y1c * 56 + x0c];
    const float v11 = mp[y1c * 56 + x1c];
    s[r][c] = (1.f - wy) * ((1.f - wx) * v00 + wx * v01) +
              wy * ((1.f - wx) * v10 + wx * v11);
  }
  __syncthreads();
  float* dst = g_tmp + b * OH * OW + xt;
  const int c = tid & 15;
  for (int y = tid >> 4; y < OH; y += 16) {
    float sum = 0.f;
#pragma unroll
    for (int j = 0; j < KS; j++) sum += w[j] * s[y + j][c];
    dst[y * OW + c] = sum * inv;
  }
}

// ---------------------------------------------------------------------------
// Kernel 3: horizontal blur + per-batch max.
// ---------------------------------------------------------------------------
__global__ __launch_bounds__(256) void blur_h_kernel(float* __restrict__ out_mask,
                                                     float* __restrict__ score) {
  __shared__ float s[8][256];
  __shared__ float w[KS];
  __shared__ float inv;
  __shared__ float smx[8];
  load_weights(w, &inv);
  const int tid = threadIdx.x;
  const int b = blockIdx.x / 28;
  const int yt = (blockIdx.x % 28) * 8;
  const float* src = g_tmp + (b * OH + yt) * OW;
#pragma unroll
  for (int li = tid; li < 8 * 256; li += 256) {
    const int r = li >> 8, c = li & 255;
    const int gx = reflect101(c - RR);
    s[r][c] = src[r * OW + gx];
  }
  __syncthreads();
  float* dst = out_mask + (b * OH + yt) * OW;
  const int lane = tid & 31;
  const int r = tid >> 5;
  float mx = 0.f;
#pragma unroll
  for (int x0 = 0; x0 < OW; x0 += 32) {
    const int x = x0 + lane;
    float sum = 0.f;
#pragma unroll
    for (int j = 0; j < KS; j++) sum += w[j] * s[r][x + j];
    sum *= inv;
    dst[r * OW + x] = sum;
    mx = fmaxf(mx, sum);
  }
#pragma unroll
  for (int off = 16; off > 0; off >>= 1)
    mx = fmaxf(mx, __shfl_down_sync(0xffffffffu, mx, off));
  if (lane == 0) smx[r] = mx;
  __syncthreads();
  if (tid == 0) {
    float m2 = smx[0];
#pragma unroll
    for (int k = 1; k < 8; k++) m2 = fmaxf(m2, smx[k]);
    atomicMax((int*)&score[b], __float_as_int(m2));
  }
}

extern "C" void kernel_launch(void* const* d_in, const int* in_sizes, int n_in,
                              void* d_out, int out_size) {
  const float* inputs = (const float*)d_in[0];    // [16,56,56,256]
  const float* mean = (const float*)d_in[1];      // [3136,256]
  const float* cvar_inv = (const float*)d_in[2];  // [3136,256,256]
  float* out = (float*)d_out;
  float* score = out;          // [16,1]
  float* mask = out + NB;      // [16,224,224,1]

  maha_kernel<<<HW, 256>>>(inputs, mean, cvar_inv);
  blur_v_kernel<<<16 * 14, 256>>>(score);
  blur_h_kernel<<<16 * 28, 256>>>(mask, score);
}